// round 12
// baseline (speedup 1.0000x reference)
#include <cuda_runtime.h>
#include <math.h>

#define EPSV 1e-20f

#define BB 16
#define H0 352
#define W0 1216
#define H1 176
#define W1 608
#define H2 88
#define W2 304
#define H3 44
#define W3 152

#define P0 (H0*W0)
#define P1 (H1*W1)
#define P2 (H2*W2)
#define P3 (H3*W3)

#define M0 ((size_t)BB*2*P0)
#define M1 ((size_t)BB*2*P1)
#define M2 ((size_t)BB*2*P2)
#define M3 ((size_t)BB*2*P3)

typedef unsigned long long ull;

__device__ __align__(16) float2 g_scratch[3*M0 + 3*M1 + 3*M2 + 2*M3];
__device__ ull   g_wd[480];
__device__ float g_ws[32];

// dup-pair weight layout (ull): w1:0(50) w2:50(100) w3:150(100) w4:250(72)
// w5:322(72) w6:394(72) w7:466(4); entry OFF+(ci*K+k)*2+cout
// g_ws: sums [2*lyr+co], biases [16+2*lyr+co]

__device__ __forceinline__ ull fma2(ull a, ull b, ull c){
    ull d; asm("fma.rn.f32x2 %0, %1, %2, %3;" : "=l"(d) : "l"(a), "l"(b), "l"(c)); return d;
}
__device__ __forceinline__ void unpack2(ull v, float &a, float &b){
    asm("mov.b64 {%0,%1}, %2;" : "=f"(a), "=f"(b) : "l"(v));
}
__device__ __forceinline__ ull dupf(float w){
    float2 f2 = make_float2(w, w);
    return *(ull*)&f2;
}
__device__ __forceinline__ float sp10(float p){
    float z = 10.0f * p;
    float r = (z > 20.0f) ? z : log1pf(expf(z));
    return r * 0.1f;
}

__global__ void k_prep(const float* __restrict__ w1, const float* __restrict__ b1,
                       const float* __restrict__ w2, const float* __restrict__ b2,
                       const float* __restrict__ w3, const float* __restrict__ b3,
                       const float* __restrict__ w4, const float* __restrict__ b4,
                       const float* __restrict__ w5, const float* __restrict__ b5,
                       const float* __restrict__ w6, const float* __restrict__ b6,
                       const float* __restrict__ w7, const float* __restrict__ b7){
    const float* wp[7]={w1,w2,w3,w4,w5,w6,w7};
    const float* bp[7]={b1,b2,b3,b4,b5,b6,b7};
    const int cin[7]={1,2,2,4,4,4,2};
    const int kk [7]={25,25,25,9,9,9,1};
    const int co [7]={2,2,2,2,2,2,1};
    const int off[7]={0,50,150,250,322,394,466};
    int t=threadIdx.x;
    for(int l=0;l<7;l++){
        int n=cin[l]*kk[l];
        int tot=n*co[l];
        for(int i=t;i<tot;i+=blockDim.x){
            int c=i/n, e=i%n;
            g_wd[off[l]+e*2+c]=dupf(sp10(wp[l][c*n+e]));
        }
    }
    __syncthreads();
    if(t==0){
        for(int l=0;l<7;l++){
            int n=cin[l]*kk[l];
            for(int c=0;c<co[l];c++){
                float s=0.f;
                for(int e=0;e<n;e++){ float lo,hi; unpack2(g_wd[off[l]+e*2+c],lo,hi); s+=lo; }
                g_ws[2*l+c]=s;
                g_ws[16+2*l+c]=bp[l][c];
            }
        }
    }
}

// ---- generic 4x2 tile 5x5 conv accumulate from smem planes ----
template<int CIN>
__device__ __forceinline__ void tile5_acc(const float2* __restrict__ sp, int planeSz, int sw,
                                          const ull* __restrict__ w,
                                          int tx4, int ty2, ull acc[2][2][4]){
    #pragma unroll
    for(int a=0;a<2;a++)
      #pragma unroll
      for(int dy=0;dy<2;dy++)
        #pragma unroll
        for(int dx=0;dx<4;dx++) acc[a][dy][dx]=0ull;
    #pragma unroll
    for(int ci=0;ci<CIN;ci++){
        const float2* s = sp + ci*planeSz;
        ull v[2][8];
        {
            const longlong2* p = (const longlong2*)&s[ty2*sw + tx4];
            #pragma unroll
            for(int j=0;j<4;j++){ longlong2 q=p[j]; v[0][2*j]=(ull)q.x; v[0][2*j+1]=(ull)q.y; }
        }
        #pragma unroll
        for(int ky=0;ky<5;ky++){
            const int cur = ky & 1, nxt = (ky+1) & 1;
            {
                const longlong2* p = (const longlong2*)&s[(ty2+ky+1)*sw + tx4];
                #pragma unroll
                for(int j=0;j<4;j++){ longlong2 q=p[j]; v[nxt][2*j]=(ull)q.x; v[nxt][2*j+1]=(ull)q.y; }
            }
            #pragma unroll
            for(int kx=0;kx<5;kx++){
                longlong2 wp = *(const longlong2*)&w[(ci*25 + ky*5 + kx)*2];
                ull wa=(ull)wp.x, wb=(ull)wp.y;
                #pragma unroll
                for(int dx=0;dx<4;dx++){
                    acc[0][0][dx]=fma2(wa, v[cur][kx+dx], acc[0][0][dx]);
                    acc[1][0][dx]=fma2(wb, v[cur][kx+dx], acc[1][0][dx]);
                    acc[0][1][dx]=fma2(wa, v[nxt][kx+dx], acc[0][1][dx]);
                    acc[1][1][dx]=fma2(wb, v[nxt][kx+dx], acc[1][1][dx]);
                }
            }
        }
    }
}

// mid-stage epilogue: write (c, x*c) into smem plane, zero outside image
__device__ __forceinline__ void epi_mid(ull acc[2][2][4], float2* dst, int planeSz, int dw,
                                        int tx4, int ty2,
                                        float rs0, float rs1, float bi0, float bi1,
                                        int gx0, int gy0, int W, int H){
    #pragma unroll
    for(int a=0;a<2;a++){
        float rsa = a?rs1:rs0, bia = a?bi1:bi0;
        #pragma unroll
        for(int dy=0;dy<2;dy++){
            int gy = gy0 + ty2 + dy;
            bool rowok = (unsigned)gy < (unsigned)H;
            float2 o[4];
            #pragma unroll
            for(int j=0;j<2;j++){
                float d0,n0,d1,n1;
                unpack2(acc[a][dy][2*j],   d0, n0);
                unpack2(acc[a][dy][2*j+1], d1, n1);
                float x0 = n0/(d0+EPSV)+bia, c0 = d0*rsa;
                float x1 = n1/(d1+EPSV)+bia, c1 = d1*rsa;
                o[2*j]   = make_float2(c0, x0*c0);
                o[2*j+1] = make_float2(c1, x1*c1);
            }
            #pragma unroll
            for(int dx=0;dx<4;dx++){
                int gx = gx0 + tx4 + dx;
                if(!rowok || (unsigned)gx >= (unsigned)W) o[dx] = make_float2(0.f,0.f);
            }
            float4* p = (float4*)&dst[a*planeSz + (ty2+dy)*dw + tx4];
            p[0] = make_float4(o[0].x,o[0].y,o[1].x,o[1].y);
            p[1] = make_float4(o[2].x,o[2].y,o[3].x,o[3].y);
        }
    }
}

// ---------------- fused encoder: [conv1] -> conv2 -> conv3 (+pool) ----------
// 256 threads, output tile 64x32. Stages in smem.
#define I0W 76
#define I0H 44
#define M1W 72
#define M1H 40
#define M2W 68
#define M2H 36
#define ENC_SMEM (2000 + 128 + 2*M1H*M1W*8 + 2*M2H*M2W*8)  // 87376

template<bool C1, bool POOL>
__global__ void __launch_bounds__(256,2)
k_enc(const float2* __restrict__ in2, const float* __restrict__ xs, const float* __restrict__ cs,
      float2* __restrict__ out, float2* __restrict__ outds,
      int H, int W, int bpr, int bpc){
    extern __shared__ __align__(16) char dyn[];
    ull*    wpk  = (ull*)dyn;                         // 250 ull
    float*  wexs = (float*)(dyn + 2000);              // 32 floats
    float2* bufA = (float2*)(dyn + 2128);             // 2 planes M1H*M1W
    float2* bufB = bufA + 2*M1H*M1W;                  // union(in0 1pl I0, mid2 2pl M2)

    const int t = threadIdx.x;
    const int P = H*W;
    for(int i=t;i<250;i+=256) wpk[i]=g_wd[i];
    if(t<32) wexs[t]=g_ws[t];

    int bx = blockIdx.x % bpr;
    int tmp = blockIdx.x / bpr;
    int by = tmp % bpc;
    int b  = tmp / bpc;
    const int OX = bx*64, OY = by*32;
    const int fx = t & 31, fy = t >> 5;

    if(C1){
        // fill in0 (bufB): 1 plane 76x44 @ (OX-6, OY-6) from split x/c
        int gx0 = OX-6, gy0 = OY-6;
        const float* cb = cs + (size_t)b*P;
        const float* xb = xs + (size_t)b*P;
        bool inter = gx0>=0 && gy0>=0 && gx0+I0W<=W && gy0+I0H<=H;
        if(inter){
            #pragma unroll
            for(int ly=fy; ly<I0H; ly+=8){
                const float* crow = cb + (size_t)(gy0+ly)*W + gx0;
                const float* xrow = xb + (size_t)(gy0+ly)*W + gx0;
                float2* srow = &bufB[ly*I0W];
                #pragma unroll
                for(int lx=fx; lx<I0W; lx+=32){
                    float c = crow[lx];
                    srow[lx] = make_float2(c, xrow[lx]*c);
                }
            }
        } else {
            #pragma unroll
            for(int ly=fy; ly<I0H; ly+=8){
                int gy = gy0+ly;
                float2* srow = &bufB[ly*I0W];
                #pragma unroll
                for(int lx=fx; lx<I0W; lx+=32){
                    int gx = gx0+lx;
                    float c=0.f,d=0.f;
                    if((unsigned)gx<(unsigned)W && (unsigned)gy<(unsigned)H){
                        int o=gy*W+gx; c=cb[o]; d=xb[o]*c;
                    }
                    srow[lx]=make_float2(c,d);
                }
            }
        }
        __syncthreads();
        // conv1: bufB(1pl,76) -> bufA(2pl,72x40), 18x20=360 tiles, lyr0 w@0
        float rs0=1.0f/wexs[0], rs1=1.0f/wexs[1], bi0=wexs[16], bi1=wexs[17];
        int gx0m = OX-4, gy0m = OY-4;
        for(int idx=t; idx<360; idx+=256){
            int tx4 = (idx % 18)*4, ty2 = (idx / 18)*2;
            ull acc[2][2][4];
            tile5_acc<1>(bufB, 0, I0W, wpk, tx4, ty2, acc);
            epi_mid(acc, bufA, M1H*M1W, M1W, tx4, ty2, rs0,rs1,bi0,bi1, gx0m, gy0m, W, H);
        }
        __syncthreads();
    } else {
        // fill bufA: 2 planes 72x40 @ (OX-4, OY-4) from interleaved in2
        int gx0 = OX-4, gy0 = OY-4;
        bool inter = gx0>=0 && gy0>=0 && gx0+M1W<=W && gy0+M1H<=H;
        #pragma unroll
        for(int ci=0;ci<2;ci++){
            const float2* src = in2 + (size_t)(b*2+ci)*P;
            float2* dstp = bufA + ci*(M1H*M1W);
            if(inter){
                #pragma unroll
                for(int ly=fy; ly<M1H; ly+=8){
                    const float4* grow = (const float4*)(src + (size_t)(gy0+ly)*W + gx0);
                    float4* srow = (float4*)&dstp[ly*M1W];
                    #pragma unroll
                    for(int j=fx; j<M1W/2; j+=32) srow[j]=grow[j];
                }
            } else {
                #pragma unroll
                for(int ly=fy; ly<M1H; ly+=8){
                    int gy = gy0+ly;
                    float2* srow = &dstp[ly*M1W];
                    #pragma unroll
                    for(int lx=fx; lx<M1W; lx+=32){
                        int gx = gx0+lx;
                        float2 v = make_float2(0.f,0.f);
                        if((unsigned)gx<(unsigned)W && (unsigned)gy<(unsigned)H)
                            v = src[(size_t)gy*W+gx];
                        srow[lx]=v;
                    }
                }
            }
        }
        __syncthreads();
    }

    // conv2: bufA(2pl,72x40) -> bufB as mid2(2pl,68x36), 17x18=306 tiles, lyr1 w@50
    {
        float rs0=1.0f/wexs[2], rs1=1.0f/wexs[3], bi0=wexs[18], bi1=wexs[19];
        int gx0m = OX-2, gy0m = OY-2;
        for(int idx=t; idx<306; idx+=256){
            int tx4 = (idx % 17)*4, ty2 = (idx / 17)*2;
            ull acc[2][2][4];
            tile5_acc<2>(bufA, M1H*M1W, M1W, wpk+50, tx4, ty2, acc);
            epi_mid(acc, bufB, M2H*M2W, M2W, tx4, ty2, rs0,rs1,bi0,bi1, gx0m, gy0m, W, H);
        }
        __syncthreads();
    }

    // conv3: bufB(2pl,68x36) -> global out (+pool), 16x16=256 tiles exact, lyr2 w@150
    {
        float rs0=1.0f/wexs[4], rs1=1.0f/wexs[5], bi0=wexs[20], bi1=wexs[21];
        int tx4 = (t & 15)*4, ty2 = (t >> 4)*2;
        ull acc[2][2][4];
        tile5_acc<2>(bufB, M2H*M2W, M2W, wpk+150, tx4, ty2, acc);

        int gx = OX + tx4;
        int gyp = OY + ty2;
        if(gx < W && gyp < H){
            const int Wh = W>>1;
            const int Ph = Wh*(H>>1);
            #pragma unroll
            for(int a=0;a<2;a++){
                float rsa = a ? rs1 : rs0;
                float bia = a ? bi1 : bi0;
                float rx[2][4], rc[2][4];
                #pragma unroll
                for(int dy=0;dy<2;dy++){
                    #pragma unroll
                    for(int j=0;j<2;j++){
                        float d0,n0,d1,n1;
                        unpack2(acc[a][dy][2*j],   d0, n0);
                        unpack2(acc[a][dy][2*j+1], d1, n1);
                        rx[dy][2*j]   = n0/(d0+EPSV)+bia;
                        rx[dy][2*j+1] = n1/(d1+EPSV)+bia;
                        rc[dy][2*j]   = d0*rsa;
                        rc[dy][2*j+1] = d1*rsa;
                    }
                    float4* dst = (float4*)(out + (size_t)(b*2+a)*P + (size_t)(gyp+dy)*W + gx);
                    dst[0] = make_float4(rc[dy][0], rx[dy][0]*rc[dy][0],
                                         rc[dy][1], rx[dy][1]*rc[dy][1]);
                    dst[1] = make_float4(rc[dy][2], rx[dy][2]*rc[dy][2],
                                         rc[dy][3], rx[dy][3]*rc[dy][3]);
                }
                if(POOL){
                    float pc[2], px[2];
                    #pragma unroll
                    for(int cell=0;cell<2;cell++){
                        int c0 = 2*cell;
                        float bc = rc[0][c0],  bxv = rx[0][c0];
                        if(rc[0][c0+1]>bc){ bc=rc[0][c0+1]; bxv=rx[0][c0+1]; }
                        if(rc[1][c0]  >bc){ bc=rc[1][c0];   bxv=rx[1][c0];   }
                        if(rc[1][c0+1]>bc){ bc=rc[1][c0+1]; bxv=rx[1][c0+1]; }
                        pc[cell] = bc*0.25f;
                        px[cell] = bxv;
                    }
                    float4* pdst = (float4*)(outds + (size_t)(b*2+a)*Ph + (size_t)(gyp>>1)*Wh + (gx>>1));
                    pdst[0] = make_float4(pc[0], px[0]*pc[0], pc[1], px[1]*pc[1]);
                }
            }
        }
    }
}

// ---------------- tiled 5x5 nconv (L2/L3 levels), from R11 -----------------
#define TX5 64
#define TY5 16
#define SW5 (TX5+4)
#define SH5 (TY5+4)

template<int CIN, int WOFF, int LYR, bool POOL>
__global__ void __launch_bounds__(128,6)
k_nconv5t(const float2* __restrict__ in,
          float2* __restrict__ out, float2* __restrict__ outds,
          int H, int W, int bpr, int bpc){
    __shared__ __align__(16) float2 sm[CIN][SH5*SW5];
    __shared__ __align__(16) ull wpk2[2*CIN*25];
    __shared__ float wex[4];

    const int t = threadIdx.x;
    const int P = H*W;

    for(int i=t;i<2*CIN*25;i+=128) wpk2[i]=g_wd[WOFF+i];
    if(t<2){ wex[t]=g_ws[2*LYR+t]; wex[2+t]=g_ws[16+2*LYR+t]; }

    int bx = blockIdx.x % bpr;
    int tmp = blockIdx.x / bpr;
    int by = tmp % bpc;
    int b  = tmp / bpc;
    int gx0 = bx*TX5 - 2;
    int gy0 = by*TY5 - 2;

    const bool inter = (gx0>=0) && (gy0>=0) && (gx0+SW5<=W) && (gy0+SH5<=H);
    const int fx = t & 31, fy = t >> 5;

    #pragma unroll
    for(int ci=0;ci<CIN;ci++){
        const float2* src = in + (size_t)(b*CIN+ci)*P;
        if(inter){
            #pragma unroll
            for(int ly=fy; ly<SH5; ly+=4){
                const float4* grow = (const float4*)(src + (size_t)(gy0+ly)*W + gx0);
                float4* srow = (float4*)&sm[ci][ly*SW5];
                #pragma unroll
                for(int j=fx; j<SW5/2; j+=32) srow[j] = grow[j];
            }
        } else {
            #pragma unroll
            for(int ly=fy; ly<SH5; ly+=4){
                int gy = gy0+ly;
                float2* srow = &sm[ci][ly*SW5];
                #pragma unroll
                for(int lx=fx; lx<SW5; lx+=32){
                    int gx = gx0+lx;
                    float2 v = make_float2(0.f, 0.f);
                    if((unsigned)gx<(unsigned)W && (unsigned)gy<(unsigned)H)
                        v = src[(size_t)gy*W+gx];
                    srow[lx] = v;
                }
            }
        }
    }
    __syncthreads();

    const int tx = (t & 15)*4;
    const int ty = (t >> 4)*2;

    ull acc[2][2][4];
    tile5_acc<CIN>(&sm[0][0], SH5*SW5, SW5, wpk2, tx, ty, acc);

    float rs0 = 1.0f/wex[0];
    float rs1 = 1.0f/wex[1];
    int gx = bx*TX5 + tx;
    int gyp = by*TY5 + ty;
    if(gx < W && gyp < H){
        const int Wh = W>>1;
        const int Ph = Wh*(H>>1);
        #pragma unroll
        for(int a=0;a<2;a++){
            float rsa = a ? rs1 : rs0;
            float bia = wex[2+a];
            float rx[2][4], rc[2][4];
            #pragma unroll
            for(int dy=0;dy<2;dy++){
                #pragma unroll
                for(int j=0;j<2;j++){
                    float d0,n0,d1,n1;
                    unpack2(acc[a][dy][2*j],   d0, n0);
                    unpack2(acc[a][dy][2*j+1], d1, n1);
                    rx[dy][2*j]   = n0/(d0+EPSV)+bia;
                    rx[dy][2*j+1] = n1/(d1+EPSV)+bia;
                    rc[dy][2*j]   = d0*rsa;
                    rc[dy][2*j+1] = d1*rsa;
                }
                float4* dst = (float4*)(out + (size_t)(b*2+a)*P + (size_t)(gyp+dy)*W + gx);
                dst[0] = make_float4(rc[dy][0], rx[dy][0]*rc[dy][0],
                                     rc[dy][1], rx[dy][1]*rc[dy][1]);
                dst[1] = make_float4(rc[dy][2], rx[dy][2]*rc[dy][2],
                                     rc[dy][3], rx[dy][3]*rc[dy][3]);
            }
            if(POOL){
                float pc[2], px[2];
                #pragma unroll
                for(int cell=0;cell<2;cell++){
                    int c0 = 2*cell;
                    float bc = rc[0][c0],  bxv = rx[0][c0];
                    if(rc[0][c0+1]>bc){ bc=rc[0][c0+1]; bxv=rx[0][c0+1]; }
                    if(rc[1][c0]  >bc){ bc=rc[1][c0];   bxv=rx[1][c0];   }
                    if(rc[1][c0+1]>bc){ bc=rc[1][c0+1]; bxv=rx[1][c0+1]; }
                    pc[cell] = bc*0.25f;
                    px[cell] = bxv;
                }
                float4* pdst = (float4*)(outds + (size_t)(b*2+a)*Ph + (size_t)(gyp>>1)*Wh + (gx>>1));
                pdst[0] = make_float4(pc[0], px[0]*pc[0], pc[1], px[1]*pc[1]);
            }
        }
    }
}

// ---------------- tiled 3x3 cat nconv + opt fused 1x1 (from R11) -----------
#define TX3 64
#define TY3 16
#define SW3 (TX3+2)
#define SH3 (TY3+2)

template<bool UP_FIRST, int WOFF, int LYR, bool FUSE_OUT>
__global__ void __launch_bounds__(128,6)
k_nconv3t(const float2* __restrict__ na, const float2* __restrict__ ub,
          float2* __restrict__ out,
          float* __restrict__ xof, float* __restrict__ cof,
          int H, int W, int bpr, int bpc){
    __shared__ __align__(16) float2 sm[4][SH3*SW3];
    __shared__ __align__(16) ull wpk2[72];
    __shared__ float wex[8];

    const int t = threadIdx.x;
    const int P = H*W;
    const int Wh = W>>1, Ph = (W>>1)*(H>>1);

    for(int i=t;i<72;i+=128) wpk2[i]=g_wd[WOFF+i];
    if(t<2){ wex[t]=g_ws[2*LYR+t]; wex[2+t]=g_ws[16+2*LYR+t]; }
    if(FUSE_OUT && t==0){
        float lo, hi;
        unpack2(g_wd[466], lo, hi); wex[4]=lo;
        unpack2(g_wd[468], lo, hi); wex[5]=lo;
        wex[6]=1.0f/g_ws[12];
        wex[7]=g_ws[28];
    }

    int bx = blockIdx.x % bpr;
    int tmp = blockIdx.x / bpr;
    int by = tmp % bpc;
    int b  = tmp / bpc;
    int gx0 = bx*TX3 - 1;
    int gy0 = by*TY3 - 1;

    const bool inter = (gx0>=0) && (gy0>=0) && (gx0+SW3<=W) && (gy0+SH3<=H);
    const int fx = t & 31, fy = t >> 5;

    #pragma unroll
    for(int ci=0;ci<4;ci++){
        const bool fromUp = UP_FIRST ? (ci<2) : (ci>=2);
        const int ch = fromUp ? (UP_FIRST ? ci : ci-2) : (UP_FIRST ? ci-2 : ci);
        const float2* src = fromUp ? (ub + (size_t)(b*2+ch)*Ph) : (na + (size_t)(b*2+ch)*P);
        if(inter){
            #pragma unroll
            for(int ly=fy; ly<SH3; ly+=4){
                int gy = gy0+ly;
                float2* srow = &sm[ci][ly*SW3];
                if(fromUp){
                    const float2* grow = src + (size_t)(gy>>1)*Wh;
                    #pragma unroll
                    for(int lx=fx; lx<SW3; lx+=32)
                        srow[lx] = grow[(gx0+lx)>>1];
                } else {
                    const float2* grow = src + (size_t)gy*W + gx0;
                    #pragma unroll
                    for(int lx=fx; lx<SW3; lx+=32)
                        srow[lx] = grow[lx];
                }
            }
        } else {
            #pragma unroll
            for(int ly=fy; ly<SH3; ly+=4){
                int gy = gy0+ly;
                float2* srow = &sm[ci][ly*SW3];
                #pragma unroll
                for(int lx=fx; lx<SW3; lx+=32){
                    int gx = gx0+lx;
                    float2 v = make_float2(0.f, 0.f);
                    if((unsigned)gx<(unsigned)W && (unsigned)gy<(unsigned)H)
                        v = fromUp ? src[(size_t)(gy>>1)*Wh + (gx>>1)]
                                   : src[(size_t)gy*W + gx];
                    srow[lx] = v;
                }
            }
        }
    }
    __syncthreads();

    const int tx = (t & 15)*4;
    const int ty = (t >> 4)*2;

    ull acc[2][2][4];
    #pragma unroll
    for(int a=0;a<2;a++)
      #pragma unroll
      for(int dy=0;dy<2;dy++)
        #pragma unroll
        for(int dx=0;dx<4;dx++) acc[a][dy][dx]=0ull;

    #pragma unroll
    for(int ci=0;ci<4;ci++){
        ull v[2][6];
        {
            const longlong2* p = (const longlong2*)&sm[ci][ty*SW3 + tx];
            #pragma unroll
            for(int j=0;j<3;j++){ longlong2 q=p[j]; v[0][2*j]=(ull)q.x; v[0][2*j+1]=(ull)q.y; }
        }
        #pragma unroll
        for(int ky=0;ky<3;ky++){
            const int cur = ky & 1, nxt = (ky+1) & 1;
            {
                const longlong2* p = (const longlong2*)&sm[ci][(ty+ky+1)*SW3 + tx];
                #pragma unroll
                for(int j=0;j<3;j++){ longlong2 q=p[j]; v[nxt][2*j]=(ull)q.x; v[nxt][2*j+1]=(ull)q.y; }
            }
            #pragma unroll
            for(int kx=0;kx<3;kx++){
                longlong2 wp = *(const longlong2*)&wpk2[(ci*9 + ky*3 + kx)*2];
                ull wa=(ull)wp.x, wb=(ull)wp.y;
                #pragma unroll
                for(int dx=0;dx<4;dx++){
                    acc[0][0][dx]=fma2(wa, v[cur][kx+dx], acc[0][0][dx]);
                    acc[1][0][dx]=fma2(wb, v[cur][kx+dx], acc[1][0][dx]);
                    acc[0][1][dx]=fma2(wa, v[nxt][kx+dx], acc[0][1][dx]);
                    acc[1][1][dx]=fma2(wb, v[nxt][kx+dx], acc[1][1][dx]);
                }
            }
        }
    }

    float rs0 = 1.0f/wex[0];
    float rs1 = 1.0f/wex[1];
    float bi0 = wex[2];
    float bi1 = wex[3];
    int gx = bx*TX3 + tx;
    if(gx < W){
        #pragma unroll
        for(int dy=0;dy<2;dy++){
            int gy = by*TY3 + ty + dy;
            if(gy>=H) continue;
            float xc[2][4], cc[2][4];
            #pragma unroll
            for(int a=0;a<2;a++){
                float d0,n0,d1,n1,d2,n2,d3,n3;
                unpack2(acc[a][dy][0], d0, n0);
                unpack2(acc[a][dy][1], d1, n1);
                unpack2(acc[a][dy][2], d2, n2);
                unpack2(acc[a][dy][3], d3, n3);
                float bia = a ? bi1 : bi0;
                float rsa = a ? rs1 : rs0;
                xc[a][0] = n0/(d0+EPSV)+bia; xc[a][1] = n1/(d1+EPSV)+bia;
                xc[a][2] = n2/(d2+EPSV)+bia; xc[a][3] = n3/(d3+EPSV)+bia;
                cc[a][0] = d0*rsa; cc[a][1] = d1*rsa;
                cc[a][2] = d2*rsa; cc[a][3] = d3*rsa;
            }
            if(!FUSE_OUT){
                #pragma unroll
                for(int a=0;a<2;a++){
                    float4* dst = (float4*)(out + (size_t)(b*2+a)*P + (size_t)gy*W + gx);
                    dst[0] = make_float4(cc[a][0], xc[a][0]*cc[a][0],
                                         cc[a][1], xc[a][1]*cc[a][1]);
                    dst[1] = make_float4(cc[a][2], xc[a][2]*cc[a][2],
                                         cc[a][3], xc[a][3]*cc[a][3]);
                }
            } else {
                float w70 = wex[4], w71 = wex[5], rs7 = wex[6], bi7 = wex[7];
                float4 XO, CO;
                #pragma unroll
                for(int k=0;k<4;k++){
                    float den = w70*cc[0][k] + w71*cc[1][k];
                    float nom = w70*xc[0][k]*cc[0][k] + w71*xc[1][k]*cc[1][k];
                    ((float*)&XO)[k] = nom/(den+EPSV) + bi7;
                    ((float*)&CO)[k] = den*rs7;
                }
                size_t o = (size_t)b*P + (size_t)gy*W + gx;
                *(float4*)&xof[o] = XO;
                *(float4*)&cof[o] = CO;
            }
        }
    }
}

extern "C" void kernel_launch(void* const* d_in, const int* in_sizes, int n_in,
                              void* d_out, int out_size){
    const float* x0 = (const float*)d_in[0];
    const float* c0 = (const float*)d_in[1];
    const float* w1 = (const float*)d_in[2];  const float* b1 = (const float*)d_in[3];
    const float* w2 = (const float*)d_in[4];  const float* b2 = (const float*)d_in[5];
    const float* w3 = (const float*)d_in[6];  const float* b3 = (const float*)d_in[7];
    const float* w4 = (const float*)d_in[8];  const float* b4 = (const float*)d_in[9];
    const float* w5 = (const float*)d_in[10]; const float* b5 = (const float*)d_in[11];
    const float* w6 = (const float*)d_in[12]; const float* b6 = (const float*)d_in[13];
    const float* w7 = (const float*)d_in[14]; const float* b7 = (const float*)d_in[15];

    float2* S = nullptr;  cudaGetSymbolAddress((void**)&S,  g_scratch);

    float2 *T1 = S + 2*M0;
    float2 *HA = S + 3*M0, *T2 = HA + 2*M1;
    float2 *Q  = HA + 3*M1,*T3 = Q + M2,     *T34= Q + 2*M2;
    float2 *E  = Q + 3*M2, *T4 = E + M3;

    static bool attr_set = false;
    if(!attr_set){
        cudaFuncSetAttribute(k_enc<true,true>,  cudaFuncAttributeMaxDynamicSharedMemorySize, ENC_SMEM);
        cudaFuncSetAttribute(k_enc<false,true>, cudaFuncAttributeMaxDynamicSharedMemorySize, ENC_SMEM);
        attr_set = true;
    }

    k_prep<<<1,128>>>(w1,b1,w2,b2,w3,b3,w4,b4,w5,b5,w6,b6,w7,b7);

    int bpr, bpc, g;

    // fused encoder, full res: conv1->conv2->conv3 + pool -> T1, HA
    bpr = W0/64; bpc = H0/32; g = bpr*bpc*BB;               // 19 x 11, exact
    k_enc<true,true><<<g,256,ENC_SMEM>>>(nullptr, x0, c0, T1, HA, H0, W0, bpr, bpc);

    // fused L1: conv2->conv3 + pool -> T2, Q
    bpr = (W1+63)/64; bpc = (H1+31)/32; g = bpr*bpc*BB;     // 10 x 6
    k_enc<false,true><<<g,256,ENC_SMEM>>>(HA, nullptr, nullptr, T2, Q, H1, W1, bpr, bpc);

    // level 2: conv w2 + pool -> T3, E
    bpr = (W2+TX5-1)/TX5; bpc = (H2+TY5-1)/TY5; g = bpr*bpc*BB;
    k_nconv5t<2,50,1,true> <<<g,128>>>(Q, T3, E, H2, W2, bpr, bpc);

    // level 3: conv w2 -> T4
    bpr = (W3+TX5-1)/TX5; bpc = (H3+TY5-1)/TY5; g = bpr*bpc*BB;
    k_nconv5t<2,50,1,false><<<g,128>>>(E, T4, nullptr, H3, W3, bpr, bpc);

    // decoder
    float* out = (float*)d_out;
    bpr = (W2+TX3-1)/TX3; bpc = (H2+TY3-1)/TY3; g = bpr*bpc*BB;
    k_nconv3t<false,250,3,false><<<g,128>>>(T3, T4,  T34, nullptr, nullptr, H2, W2, bpr, bpc);
    bpr = (W1+TX3-1)/TX3; bpc = (H1+TY3-1)/TY3; g = bpr*bpc*BB;
    k_nconv3t<false,322,4,false><<<g,128>>>(T2, T34, HA,  nullptr, nullptr, H1, W1, bpr, bpc);
    bpr = (W0+TX3-1)/TX3; bpc = (H0+TY3-1)/TY3; g = bpr*bpc*BB;
    k_nconv3t<true,394,5,true>  <<<g,128>>>(T1, HA,  nullptr,
                                            out, out + (size_t)BB*P0, H0, W0, bpr, bpc);
}

// round 13
// speedup vs baseline: 1.1467x; 1.1467x over previous
#include <cuda_runtime.h>
#include <math.h>

#define EPSV 1e-20f

#define BB 16
#define H0 352
#define W0 1216
#define H1 176
#define W1 608
#define H2 88
#define W2 304
#define H3 44
#define W3 152

#define P0 (H0*W0)
#define P1 (H1*W1)
#define P2 (H2*W2)
#define P3 (H3*W3)

// float2 element counts per interleaved (c, x*c) tensor
#define M0 ((size_t)BB*2*P0)
#define M1 ((size_t)BB*2*P1)
#define M2 ((size_t)BB*2*P2)
#define M3 ((size_t)BB*2*P3)

typedef unsigned long long ull;

__device__ __align__(16) float2 g_scratch[3*M0 + 3*M1 + 3*M2 + 2*M3];
__device__ ull   g_wd[480];
__device__ float g_ws[32];

// dup-pair weight layout (ull units):
// w1:0(50) w2:50(100) w3:150(100) w4:250(72) w5:322(72) w6:394(72) w7:466(4)
// entry: OFF + (ci*K + k)*2 + cout
// g_ws: sums at [2*lyr + co], biases at [16 + 2*lyr + co]

__device__ __forceinline__ ull fma2(ull a, ull b, ull c){
    ull d; asm("fma.rn.f32x2 %0, %1, %2, %3;" : "=l"(d) : "l"(a), "l"(b), "l"(c)); return d;
}
__device__ __forceinline__ void unpack2(ull v, float &a, float &b){
    asm("mov.b64 {%0,%1}, %2;" : "=f"(a), "=f"(b) : "l"(v));
}
__device__ __forceinline__ ull dupf(float w){
    float2 f2 = make_float2(w, w);
    return *(ull*)&f2;
}
__device__ __forceinline__ float sp10(float p){
    float z = 10.0f * p;
    float r = (z > 20.0f) ? z : log1pf(expf(z));
    return r * 0.1f;
}

__global__ void k_prep(const float* __restrict__ w1, const float* __restrict__ b1,
                       const float* __restrict__ w2, const float* __restrict__ b2,
                       const float* __restrict__ w3, const float* __restrict__ b3,
                       const float* __restrict__ w4, const float* __restrict__ b4,
                       const float* __restrict__ w5, const float* __restrict__ b5,
                       const float* __restrict__ w6, const float* __restrict__ b6,
                       const float* __restrict__ w7, const float* __restrict__ b7){
    const float* wp[7]={w1,w2,w3,w4,w5,w6,w7};
    const float* bp[7]={b1,b2,b3,b4,b5,b6,b7};
    const int cin[7]={1,2,2,4,4,4,2};
    const int kk [7]={25,25,25,9,9,9,1};
    const int co [7]={2,2,2,2,2,2,1};
    const int off[7]={0,50,150,250,322,394,466};
    int t=threadIdx.x;
    for(int l=0;l<7;l++){
        int n=cin[l]*kk[l];
        int tot=n*co[l];
        for(int i=t;i<tot;i+=blockDim.x){
            int c=i/n, e=i%n;
            g_wd[off[l]+e*2+c]=dupf(sp10(wp[l][c*n+e]));
        }
    }
    __syncthreads();
    if(t==0){
        for(int l=0;l<7;l++){
            int n=cin[l]*kk[l];
            for(int c=0;c<co[l];c++){
                float s=0.f;
                for(int e=0;e<n;e++){ float lo,hi; unpack2(g_wd[off[l]+e*2+c],lo,hi); s+=lo; }
                g_ws[2*l+c]=s;
                g_ws[16+2*l+c]=bp[l][c];
            }
        }
    }
}

// ---------------- tiled 5x5 nconv, interleaved I/O, opt. fused pool --------
// 256 threads, 64x32 output tile, 4x2 per thread.
#define TX5 64
#define TY5 32
#define SW5 (TX5+4)   // 68
#define SH5 (TY5+4)   // 36

template<int CIN, int WOFF, int LYR, bool POOL, bool SPLIT_IN>
__global__ void __launch_bounds__(256,3)
k_nconv5t(const float2* __restrict__ in, const float* __restrict__ xs, const float* __restrict__ cs,
          float2* __restrict__ out, float2* __restrict__ outds,
          int H, int W, int bpr, int bpc){
    __shared__ __align__(16) float2 sm[CIN][SH5*SW5];
    __shared__ __align__(16) ull wpk2[2*CIN*25];
    __shared__ float wex[4];

    const int t = threadIdx.x;
    const int P = H*W;

    for(int i=t;i<2*CIN*25;i+=256) wpk2[i]=g_wd[WOFF+i];
    if(t<2){ wex[t]=g_ws[2*LYR+t]; wex[2+t]=g_ws[16+2*LYR+t]; }

    int bx = blockIdx.x % bpr;
    int tmp = blockIdx.x / bpr;
    int by = tmp % bpc;
    int b  = tmp / bpc;
    int gx0 = bx*TX5 - 2;   // always even
    int gy0 = by*TY5 - 2;

    const bool inter = (gx0>=0) && (gy0>=0) && (gx0+SW5<=W) && (gy0+SH5<=H);
    const int fx = t & 31, fy = t >> 5;   // 32 x 8 fill lattice

    #pragma unroll
    for(int ci=0;ci<CIN;ci++){
        if(!SPLIT_IN){
            const float2* src = in + (size_t)(b*CIN+ci)*P;
            if(inter){
                #pragma unroll
                for(int ly=fy; ly<SH5; ly+=8){
                    const float4* grow = (const float4*)(src + (size_t)(gy0+ly)*W + gx0);
                    float4* srow = (float4*)&sm[ci][ly*SW5];
                    #pragma unroll
                    for(int j=fx; j<SW5/2; j+=32) srow[j] = grow[j];
                }
            } else {
                #pragma unroll
                for(int ly=fy; ly<SH5; ly+=8){
                    int gy = gy0+ly;
                    float2* srow = &sm[ci][ly*SW5];
                    #pragma unroll
                    for(int lx=fx; lx<SW5; lx+=32){
                        int gx = gx0+lx;
                        float2 v = make_float2(0.f, 0.f);
                        if((unsigned)gx<(unsigned)W && (unsigned)gy<(unsigned)H)
                            v = src[(size_t)gy*W+gx];
                        srow[lx] = v;
                    }
                }
            }
        } else {
            const float* cb = cs + (size_t)(b*CIN+ci)*P;
            const float* xb = xs + (size_t)(b*CIN+ci)*P;
            if(inter){
                #pragma unroll
                for(int ly=fy; ly<SH5; ly+=8){
                    const float* crow = cb + (size_t)(gy0+ly)*W + gx0;
                    const float* xrow = xb + (size_t)(gy0+ly)*W + gx0;
                    float2* srow = &sm[ci][ly*SW5];
                    #pragma unroll
                    for(int lx=fx; lx<SW5; lx+=32){
                        float c = crow[lx];
                        srow[lx] = make_float2(c, xrow[lx]*c);
                    }
                }
            } else {
                #pragma unroll
                for(int ly=fy; ly<SH5; ly+=8){
                    int gy = gy0+ly;
                    float2* srow = &sm[ci][ly*SW5];
                    #pragma unroll
                    for(int lx=fx; lx<SW5; lx+=32){
                        int gx = gx0+lx;
                        float c=0.f, d=0.f;
                        if((unsigned)gx<(unsigned)W && (unsigned)gy<(unsigned)H){
                            int o = gy*W+gx;
                            c = cb[o]; d = xb[o]*c;
                        }
                        srow[lx] = make_float2(c, d);
                    }
                }
            }
        }
    }
    __syncthreads();

    const int tx = (t & 15)*4;
    const int ty = (t >> 4)*2;    // 0..30

    ull acc[2][2][4];
    #pragma unroll
    for(int a=0;a<2;a++)
      #pragma unroll
      for(int dy=0;dy<2;dy++)
        #pragma unroll
        for(int dx=0;dx<4;dx++) acc[a][dy][dx]=0ull;

    // ky-outer, rolling two-row data buffer; each weight pair loaded ONCE.
    #pragma unroll
    for(int ci=0;ci<CIN;ci++){
        ull v[2][8];
        {
            const longlong2* p = (const longlong2*)&sm[ci][ty*SW5 + tx];
            #pragma unroll
            for(int j=0;j<4;j++){ longlong2 q=p[j]; v[0][2*j]=(ull)q.x; v[0][2*j+1]=(ull)q.y; }
        }
        #pragma unroll
        for(int ky=0;ky<5;ky++){
            const int cur = ky & 1, nxt = (ky+1) & 1;
            {
                const longlong2* p = (const longlong2*)&sm[ci][(ty+ky+1)*SW5 + tx];
                #pragma unroll
                for(int j=0;j<4;j++){ longlong2 q=p[j]; v[nxt][2*j]=(ull)q.x; v[nxt][2*j+1]=(ull)q.y; }
            }
            #pragma unroll
            for(int kx=0;kx<5;kx++){
                longlong2 wp = *(const longlong2*)&wpk2[(ci*25 + ky*5 + kx)*2];
                ull wa=(ull)wp.x, wb=(ull)wp.y;
                #pragma unroll
                for(int dx=0;dx<4;dx++){
                    acc[0][0][dx]=fma2(wa, v[cur][kx+dx], acc[0][0][dx]);
                    acc[1][0][dx]=fma2(wb, v[cur][kx+dx], acc[1][0][dx]);
                    acc[0][1][dx]=fma2(wa, v[nxt][kx+dx], acc[0][1][dx]);
                    acc[1][1][dx]=fma2(wb, v[nxt][kx+dx], acc[1][1][dx]);
                }
            }
        }
    }

    float rs0 = 1.0f/wex[0];
    float rs1 = 1.0f/wex[1];
    int gx = bx*TX5 + tx;
    int gyp = by*TY5 + ty;        // even; rows gyp, gyp+1
    if(gx < W && gyp < H){
        const int Wh = W>>1;
        const int Ph = Wh*(H>>1);
        #pragma unroll
        for(int a=0;a<2;a++){
            float rsa = a ? rs1 : rs0;
            float bia = wex[2+a];
            float rx[2][4], rc[2][4];
            #pragma unroll
            for(int dy=0;dy<2;dy++){
                #pragma unroll
                for(int j=0;j<2;j++){
                    float d0,n0,d1,n1;
                    unpack2(acc[a][dy][2*j],   d0, n0);
                    unpack2(acc[a][dy][2*j+1], d1, n1);
                    rx[dy][2*j]   = n0/(d0+EPSV)+bia;
                    rx[dy][2*j+1] = n1/(d1+EPSV)+bia;
                    rc[dy][2*j]   = d0*rsa;
                    rc[dy][2*j+1] = d1*rsa;
                }
                float4* dst = (float4*)(out + (size_t)(b*2+a)*P + (size_t)(gyp+dy)*W + gx);
                dst[0] = make_float4(rc[dy][0], rx[dy][0]*rc[dy][0],
                                     rc[dy][1], rx[dy][1]*rc[dy][1]);
                dst[1] = make_float4(rc[dy][2], rx[dy][2]*rc[dy][2],
                                     rc[dy][3], rx[dy][3]*rc[dy][3]);
            }
            if(POOL){
                float pc[2], px[2];
                #pragma unroll
                for(int cell=0;cell<2;cell++){
                    int c0 = 2*cell;
                    float bc = rc[0][c0],  bxv = rx[0][c0];
                    if(rc[0][c0+1]>bc){ bc=rc[0][c0+1]; bxv=rx[0][c0+1]; }
                    if(rc[1][c0]  >bc){ bc=rc[1][c0];   bxv=rx[1][c0];   }
                    if(rc[1][c0+1]>bc){ bc=rc[1][c0+1]; bxv=rx[1][c0+1]; }
                    pc[cell] = bc*0.25f;
                    px[cell] = bxv;
                }
                float4* pdst = (float4*)(outds + (size_t)(b*2+a)*Ph + (size_t)(gyp>>1)*Wh + (gx>>1));
                pdst[0] = make_float4(pc[0], px[0]*pc[0], pc[1], px[1]*pc[1]);
            }
        }
    }
}

// ---------------- tiled 3x3 cat nconv, interleaved I/O, opt. fused 1x1 -----
#define TX3 64
#define TY3 16
#define SW3 (TX3+2)   // 66
#define SH3 (TY3+2)   // 18

template<bool UP_FIRST, int WOFF, int LYR, bool FUSE_OUT>
__global__ void __launch_bounds__(128,6)
k_nconv3t(const float2* __restrict__ na, const float2* __restrict__ ub,
          float2* __restrict__ out,
          float* __restrict__ xof, float* __restrict__ cof,
          int H, int W, int bpr, int bpc){
    __shared__ __align__(16) float2 sm[4][SH3*SW3];
    __shared__ __align__(16) ull wpk2[72];
    __shared__ float wex[8];

    const int t = threadIdx.x;
    const int P = H*W;
    const int Wh = W>>1, Ph = (W>>1)*(H>>1);

    for(int i=t;i<72;i+=128) wpk2[i]=g_wd[WOFF+i];
    if(t<2){ wex[t]=g_ws[2*LYR+t]; wex[2+t]=g_ws[16+2*LYR+t]; }
    if(FUSE_OUT && t==0){
        float lo, hi;
        unpack2(g_wd[466], lo, hi); wex[4]=lo;       // w7_0
        unpack2(g_wd[468], lo, hi); wex[5]=lo;       // w7_1
        wex[6]=1.0f/g_ws[12];                        // 1/sum7
        wex[7]=g_ws[28];                             // bias7
    }

    int bx = blockIdx.x % bpr;
    int tmp = blockIdx.x / bpr;
    int by = tmp % bpc;
    int b  = tmp / bpc;
    int gx0 = bx*TX3 - 1;
    int gy0 = by*TY3 - 1;

    const bool inter = (gx0>=0) && (gy0>=0) && (gx0+SW3<=W) && (gy0+SH3<=H);
    const int fx = t & 31, fy = t >> 5;

    #pragma unroll
    for(int ci=0;ci<4;ci++){
        const bool fromUp = UP_FIRST ? (ci<2) : (ci>=2);
        const int ch = fromUp ? (UP_FIRST ? ci : ci-2) : (UP_FIRST ? ci-2 : ci);
        const float2* src = fromUp ? (ub + (size_t)(b*2+ch)*Ph) : (na + (size_t)(b*2+ch)*P);
        if(inter){
            #pragma unroll
            for(int ly=fy; ly<SH3; ly+=4){
                int gy = gy0+ly;
                float2* srow = &sm[ci][ly*SW3];
                if(fromUp){
                    const float2* grow = src + (size_t)(gy>>1)*Wh;
                    #pragma unroll
                    for(int lx=fx; lx<SW3; lx+=32)
                        srow[lx] = grow[(gx0+lx)>>1];
                } else {
                    const float2* grow = src + (size_t)gy*W + gx0;
                    #pragma unroll
                    for(int lx=fx; lx<SW3; lx+=32)
                        srow[lx] = grow[lx];
                }
            }
        } else {
            #pragma unroll
            for(int ly=fy; ly<SH3; ly+=4){
                int gy = gy0+ly;
                float2* srow = &sm[ci][ly*SW3];
                #pragma unroll
                for(int lx=fx; lx<SW3; lx+=32){
                    int gx = gx0+lx;
                    float2 v = make_float2(0.f, 0.f);
                    if((unsigned)gx<(unsigned)W && (unsigned)gy<(unsigned)H)
                        v = fromUp ? src[(size_t)(gy>>1)*Wh + (gx>>1)]
                                   : src[(size_t)gy*W + gx];
                    srow[lx] = v;
                }
            }
        }
    }
    __syncthreads();

    const int tx = (t & 15)*4;
    const int ty = (t >> 4)*2;

    ull acc[2][2][4];
    #pragma unroll
    for(int a=0;a<2;a++)
      #pragma unroll
      for(int dy=0;dy<2;dy++)
        #pragma unroll
        for(int dx=0;dx<4;dx++) acc[a][dy][dx]=0ull;

    #pragma unroll
    for(int ci=0;ci<4;ci++){
        ull v[2][6];
        {
            const longlong2* p = (const longlong2*)&sm[ci][ty*SW3 + tx];
            #pragma unroll
            for(int j=0;j<3;j++){ longlong2 q=p[j]; v[0][2*j]=(ull)q.x; v[0][2*j+1]=(ull)q.y; }
        }
        #pragma unroll
        for(int ky=0;ky<3;ky++){
            const int cur = ky & 1, nxt = (ky+1) & 1;
            {
                const longlong2* p = (const longlong2*)&sm[ci][(ty+ky+1)*SW3 + tx];
                #pragma unroll
                for(int j=0;j<3;j++){ longlong2 q=p[j]; v[nxt][2*j]=(ull)q.x; v[nxt][2*j+1]=(ull)q.y; }
            }
            #pragma unroll
            for(int kx=0;kx<3;kx++){
                longlong2 wp = *(const longlong2*)&wpk2[(ci*9 + ky*3 + kx)*2];
                ull wa=(ull)wp.x, wb=(ull)wp.y;
                #pragma unroll
                for(int dx=0;dx<4;dx++){
                    acc[0][0][dx]=fma2(wa, v[cur][kx+dx], acc[0][0][dx]);
                    acc[1][0][dx]=fma2(wb, v[cur][kx+dx], acc[1][0][dx]);
                    acc[0][1][dx]=fma2(wa, v[nxt][kx+dx], acc[0][1][dx]);
                    acc[1][1][dx]=fma2(wb, v[nxt][kx+dx], acc[1][1][dx]);
                }
            }
        }
    }

    float rs0 = 1.0f/wex[0];
    float rs1 = 1.0f/wex[1];
    float bi0 = wex[2];
    float bi1 = wex[3];
    int gx = bx*TX3 + tx;
    if(gx < W){
        #pragma unroll
        for(int dy=0;dy<2;dy++){
            int gy = by*TY3 + ty + dy;
            if(gy>=H) continue;
            float xc[2][4], cc[2][4];
            #pragma unroll
            for(int a=0;a<2;a++){
                float d0,n0,d1,n1,d2,n2,d3,n3;
                unpack2(acc[a][dy][0], d0, n0);
                unpack2(acc[a][dy][1], d1, n1);
                unpack2(acc[a][dy][2], d2, n2);
                unpack2(acc[a][dy][3], d3, n3);
                float bia = a ? bi1 : bi0;
                float rsa = a ? rs1 : rs0;
                xc[a][0] = n0/(d0+EPSV)+bia; xc[a][1] = n1/(d1+EPSV)+bia;
                xc[a][2] = n2/(d2+EPSV)+bia; xc[a][3] = n3/(d3+EPSV)+bia;
                cc[a][0] = d0*rsa; cc[a][1] = d1*rsa;
                cc[a][2] = d2*rsa; cc[a][3] = d3*rsa;
            }
            if(!FUSE_OUT){
                #pragma unroll
                for(int a=0;a<2;a++){
                    float4* dst = (float4*)(out + (size_t)(b*2+a)*P + (size_t)gy*W + gx);
                    dst[0] = make_float4(cc[a][0], xc[a][0]*cc[a][0],
                                         cc[a][1], xc[a][1]*cc[a][1]);
                    dst[1] = make_float4(cc[a][2], xc[a][2]*cc[a][2],
                                         cc[a][3], xc[a][3]*cc[a][3]);
                }
            } else {
                float w70 = wex[4], w71 = wex[5], rs7 = wex[6], bi7 = wex[7];
                float4 XO, CO;
                #pragma unroll
                for(int k=0;k<4;k++){
                    float den = w70*cc[0][k] + w71*cc[1][k];
                    float nom = w70*xc[0][k]*cc[0][k] + w71*xc[1][k]*cc[1][k];
                    ((float*)&XO)[k] = nom/(den+EPSV) + bi7;
                    ((float*)&CO)[k] = den*rs7;
                }
                size_t o = (size_t)b*P + (size_t)gy*W + gx;
                *(float4*)&xof[o] = XO;
                *(float4*)&cof[o] = CO;
            }
        }
    }
}

extern "C" void kernel_launch(void* const* d_in, const int* in_sizes, int n_in,
                              void* d_out, int out_size){
    const float* x0 = (const float*)d_in[0];
    const float* c0 = (const float*)d_in[1];
    const float* w1 = (const float*)d_in[2];  const float* b1 = (const float*)d_in[3];
    const float* w2 = (const float*)d_in[4];  const float* b2 = (const float*)d_in[5];
    const float* w3 = (const float*)d_in[6];  const float* b3 = (const float*)d_in[7];
    const float* w4 = (const float*)d_in[8];  const float* b4 = (const float*)d_in[9];
    const float* w5 = (const float*)d_in[10]; const float* b5 = (const float*)d_in[11];
    const float* w6 = (const float*)d_in[12]; const float* b6 = (const float*)d_in[13];
    const float* w7 = (const float*)d_in[14]; const float* b7 = (const float*)d_in[15];

    float2* S = nullptr;  cudaGetSymbolAddress((void**)&S,  g_scratch);

    float2 *A  = S,        *Bv = S + M0,     *T1 = S + 2*M0;
    float2 *HA = S + 3*M0, *HB = HA + M1,    *T2 = HA + 2*M1;
    float2 *Q  = HA + 3*M1,*T3 = Q + M2,     *T34= Q + 2*M2;
    float2 *E  = Q + 3*M2, *T4 = E + M3;

    auto tiles5 = [&](int H, int W, int &bpr, int &bpc)->int{
        bpr = (W + TX5 - 1)/TX5; bpc = (H + TY5 - 1)/TY5;
        return bpr*bpc*BB;
    };
    auto tiles3 = [&](int H, int W, int &bpr, int &bpc)->int{
        bpr = (W + TX3 - 1)/TX3; bpc = (H + TY3 - 1)/TY3;
        return bpr*bpc*BB;
    };

    k_prep<<<1,128>>>(w1,b1,w2,b2,w3,b3,w4,b4,w5,b5,w6,b6,w7,b7);

    int bpr, bpc, g;

    // encoder full res (3rd layer fuses pool -> level-1 inputs)
    g = tiles5(H0,W0,bpr,bpc);
    k_nconv5t<1,0,0,false,true>   <<<g,256>>>(nullptr, x0, c0, A, nullptr, H0, W0, bpr, bpc);
    k_nconv5t<2,50,1,false,false> <<<g,256>>>(A, nullptr, nullptr, Bv, nullptr, H0, W0, bpr, bpc);
    k_nconv5t<2,150,2,true,false> <<<g,256>>>(Bv, nullptr, nullptr, T1, HA, H0, W0, bpr, bpc);

    // level 1 (2nd layer fuses pool -> level-2 inputs)
    g = tiles5(H1,W1,bpr,bpc);
    k_nconv5t<2,50,1,false,false> <<<g,256>>>(HA, nullptr, nullptr, HB, nullptr, H1, W1, bpr, bpc);
    k_nconv5t<2,150,2,true,false> <<<g,256>>>(HB, nullptr, nullptr, T2, Q, H1, W1, bpr, bpc);

    // level 2 (fuses pool -> level-3 inputs)
    g = tiles5(H2,W2,bpr,bpc);
    k_nconv5t<2,50,1,true,false>  <<<g,256>>>(Q, nullptr, nullptr, T3, E, H2, W2, bpr, bpc);

    // level 3
    g = tiles5(H3,W3,bpr,bpc);
    k_nconv5t<2,50,1,false,false> <<<g,256>>>(E, nullptr, nullptr, T4, nullptr, H3, W3, bpr, bpc);

    // decoder (last stage fuses the final 1x1 nconv directly into d_out)
    float* out = (float*)d_out;
    g = tiles3(H2,W2,bpr,bpc);
    k_nconv3t<false,250,3,false><<<g,128>>>(T3, T4,  T34, nullptr, nullptr, H2, W2, bpr, bpc);
    g = tiles3(H1,W1,bpr,bpc);
    k_nconv3t<false,322,4,false><<<g,128>>>(T2, T34, HA,  nullptr, nullptr, H1, W1, bpr, bpc);
    g = tiles3(H0,W0,bpr,bpc);
    k_nconv3t<true,394,5,true>  <<<g,128>>>(T1, HA,  nullptr,
                                            out, out + (size_t)BB*P0, H0, W0, bpr, bpc);
}

// round 14
// speedup vs baseline: 1.2495x; 1.0896x over previous
#include <cuda_runtime.h>
#include <math.h>

#define EPSV 1e-20f

#define BB 16
#define H0 352
#define W0 1216
#define H1 176
#define W1 608
#define H2 88
#define W2 304
#define H3 44
#define W3 152

#define P0 (H0*W0)
#define P1 (H1*W1)
#define P2 (H2*W2)
#define P3 (H3*W3)

// float2 element counts per interleaved (c, x*c) tensor
#define M0 ((size_t)BB*2*P0)
#define M1 ((size_t)BB*2*P1)
#define M2 ((size_t)BB*2*P2)
#define M3 ((size_t)BB*2*P3)

typedef unsigned long long ull;

__device__ __align__(16) float2 g_scratch[3*M0 + 3*M1 + 3*M2 + 2*M3];
__device__ ull   g_wd[480];
__device__ float g_ws[32];

// dup-pair weight layout (ull units):
// w1:0(50) w2:50(100) w3:150(100) w4:250(72) w5:322(72) w6:394(72) w7:466(4)
// entry: OFF + (ci*K + k)*2 + cout
// g_ws: sums at [2*lyr + co], biases at [16 + 2*lyr + co]

__device__ __forceinline__ ull fma2(ull a, ull b, ull c){
    ull d; asm("fma.rn.f32x2 %0, %1, %2, %3;" : "=l"(d) : "l"(a), "l"(b), "l"(c)); return d;
}
__device__ __forceinline__ void unpack2(ull v, float &a, float &b){
    asm("mov.b64 {%0,%1}, %2;" : "=f"(a), "=f"(b) : "l"(v));
}
__device__ __forceinline__ ull dupf(float w){
    float2 f2 = make_float2(w, w);
    return *(ull*)&f2;
}
__device__ __forceinline__ float sp10(float p){
    float z = 10.0f * p;
    float r = (z > 20.0f) ? z : log1pf(expf(z));
    return r * 0.1f;
}

__global__ void k_prep(const float* __restrict__ w1, const float* __restrict__ b1,
                       const float* __restrict__ w2, const float* __restrict__ b2,
                       const float* __restrict__ w3, const float* __restrict__ b3,
                       const float* __restrict__ w4, const float* __restrict__ b4,
                       const float* __restrict__ w5, const float* __restrict__ b5,
                       const float* __restrict__ w6, const float* __restrict__ b6,
                       const float* __restrict__ w7, const float* __restrict__ b7){
    const float* wp[7]={w1,w2,w3,w4,w5,w6,w7};
    const float* bp[7]={b1,b2,b3,b4,b5,b6,b7};
    const int cin[7]={1,2,2,4,4,4,2};
    const int kk [7]={25,25,25,9,9,9,1};
    const int co [7]={2,2,2,2,2,2,1};
    const int off[7]={0,50,150,250,322,394,466};
    int t=threadIdx.x;
    for(int l=0;l<7;l++){
        int n=cin[l]*kk[l];
        int tot=n*co[l];
        for(int i=t;i<tot;i+=blockDim.x){
            int c=i/n, e=i%n;
            g_wd[off[l]+e*2+c]=dupf(sp10(wp[l][c*n+e]));
        }
    }
    __syncthreads();
    if(t==0){
        for(int l=0;l<7;l++){
            int n=cin[l]*kk[l];
            for(int c=0;c<co[l];c++){
                float s=0.f;
                for(int e=0;e<n;e++){ float lo,hi; unpack2(g_wd[off[l]+e*2+c],lo,hi); s+=lo; }
                g_ws[2*l+c]=s;
                g_ws[16+2*l+c]=bp[l][c];
            }
        }
    }
}

// ---------------- tiled 5x5 nconv, interleaved I/O, opt. fused pool --------
#define TX5 64
#define TY5 16
#define SW5 (TX5+4)   // 68
#define SH5 (TY5+4)   // 20

template<int CIN, int WOFF, int LYR, bool POOL, bool SPLIT_IN>
__global__ void __launch_bounds__(128,6)
k_nconv5t(const float2* __restrict__ in, const float* __restrict__ xs, const float* __restrict__ cs,
          float2* __restrict__ out, float2* __restrict__ outds,
          int H, int W, int bpr, int bpc){
    __shared__ __align__(16) float2 sm[CIN][SH5*SW5];
    __shared__ __align__(16) ull wpk2[2*CIN*25];
    __shared__ float wex[4];

    const int t = threadIdx.x;
    const int P = H*W;

    for(int i=t;i<2*CIN*25;i+=128) wpk2[i]=g_wd[WOFF+i];
    if(t<2){ wex[t]=g_ws[2*LYR+t]; wex[2+t]=g_ws[16+2*LYR+t]; }

    int bx = blockIdx.x % bpr;
    int tmp = blockIdx.x / bpr;
    int by = tmp % bpc;
    int b  = tmp / bpc;
    int gx0 = bx*TX5 - 2;   // always even
    int gy0 = by*TY5 - 2;

    const bool inter = (gx0>=0) && (gy0>=0) && (gx0+SW5<=W) && (gy0+SH5<=H);
    const int fx = t & 31, fy = t >> 5;

    #pragma unroll
    for(int ci=0;ci<CIN;ci++){
        if(!SPLIT_IN){
            const float2* src = in + (size_t)(b*CIN+ci)*P;
            if(inter){
                #pragma unroll
                for(int ly=fy; ly<SH5; ly+=4){
                    const float4* grow = (const float4*)(src + (size_t)(gy0+ly)*W + gx0);
                    float4* srow = (float4*)&sm[ci][ly*SW5];
                    #pragma unroll
                    for(int j=fx; j<SW5/2; j+=32) srow[j] = grow[j];
                }
            } else {
                #pragma unroll
                for(int ly=fy; ly<SH5; ly+=4){
                    int gy = gy0+ly;
                    float2* srow = &sm[ci][ly*SW5];
                    #pragma unroll
                    for(int lx=fx; lx<SW5; lx+=32){
                        int gx = gx0+lx;
                        float2 v = make_float2(0.f, 0.f);
                        if((unsigned)gx<(unsigned)W && (unsigned)gy<(unsigned)H)
                            v = src[(size_t)gy*W+gx];
                        srow[lx] = v;
                    }
                }
            }
        } else {
            const float* cb = cs + (size_t)(b*CIN+ci)*P;
            const float* xb = xs + (size_t)(b*CIN+ci)*P;
            if(inter){
                // vectorized: gx0 even, rows 8B-aligned -> float2 pair loads
                #pragma unroll
                for(int ly=fy; ly<SH5; ly+=4){
                    const float* crow = cb + (size_t)(gy0+ly)*W + gx0;
                    const float* xrow = xb + (size_t)(gy0+ly)*W + gx0;
                    float2* srow = &sm[ci][ly*SW5];
                    #pragma unroll
                    for(int lx=2*fx; lx<SW5; lx+=64){
                        float2 c2 = *(const float2*)&crow[lx];
                        float2 x2 = *(const float2*)&xrow[lx];
                        srow[lx]   = make_float2(c2.x, x2.x*c2.x);
                        srow[lx+1] = make_float2(c2.y, x2.y*c2.y);
                    }
                }
            } else {
                #pragma unroll
                for(int ly=fy; ly<SH5; ly+=4){
                    int gy = gy0+ly;
                    float2* srow = &sm[ci][ly*SW5];
                    #pragma unroll
                    for(int lx=fx; lx<SW5; lx+=32){
                        int gx = gx0+lx;
                        float c=0.f, d=0.f;
                        if((unsigned)gx<(unsigned)W && (unsigned)gy<(unsigned)H){
                            int o = gy*W+gx;
                            c = cb[o]; d = xb[o]*c;
                        }
                        srow[lx] = make_float2(c, d);
                    }
                }
            }
        }
    }
    __syncthreads();

    const int tx = (t & 15)*4;
    const int ty = (t >> 4)*2;

    ull acc[2][2][4];
    #pragma unroll
    for(int a=0;a<2;a++)
      #pragma unroll
      for(int dy=0;dy<2;dy++)
        #pragma unroll
        for(int dx=0;dx<4;dx++) acc[a][dy][dx]=0ull;

    // ky-outer, rolling two-row data buffer; each weight pair loaded ONCE.
    #pragma unroll
    for(int ci=0;ci<CIN;ci++){
        ull v[2][8];
        {
            const longlong2* p = (const longlong2*)&sm[ci][ty*SW5 + tx];
            #pragma unroll
            for(int j=0;j<4;j++){ longlong2 q=p[j]; v[0][2*j]=(ull)q.x; v[0][2*j+1]=(ull)q.y; }
        }
        #pragma unroll
        for(int ky=0;ky<5;ky++){
            const int cur = ky & 1, nxt = (ky+1) & 1;
            {
                const longlong2* p = (const longlong2*)&sm[ci][(ty+ky+1)*SW5 + tx];
                #pragma unroll
                for(int j=0;j<4;j++){ longlong2 q=p[j]; v[nxt][2*j]=(ull)q.x; v[nxt][2*j+1]=(ull)q.y; }
            }
            #pragma unroll
            for(int kx=0;kx<5;kx++){
                longlong2 wp = *(const longlong2*)&wpk2[(ci*25 + ky*5 + kx)*2];
                ull wa=(ull)wp.x, wb=(ull)wp.y;
                #pragma unroll
                for(int dx=0;dx<4;dx++){
                    acc[0][0][dx]=fma2(wa, v[cur][kx+dx], acc[0][0][dx]);
                    acc[1][0][dx]=fma2(wb, v[cur][kx+dx], acc[1][0][dx]);
                    acc[0][1][dx]=fma2(wa, v[nxt][kx+dx], acc[0][1][dx]);
                    acc[1][1][dx]=fma2(wb, v[nxt][kx+dx], acc[1][1][dx]);
                }
            }
        }
    }

    float rs0 = 1.0f/wex[0];
    float rs1 = 1.0f/wex[1];
    int gx = bx*TX5 + tx;
    int gyp = by*TY5 + ty;        // even; rows gyp, gyp+1
    if(gx < W && gyp < H){
        const int Wh = W>>1;
        const int Ph = Wh*(H>>1);
        #pragma unroll
        for(int a=0;a<2;a++){
            float rsa = a ? rs1 : rs0;
            float bia = wex[2+a];
            float rx[2][4], rc[2][4];
            #pragma unroll
            for(int dy=0;dy<2;dy++){
                #pragma unroll
                for(int j=0;j<2;j++){
                    float d0,n0,d1,n1;
                    unpack2(acc[a][dy][2*j],   d0, n0);
                    unpack2(acc[a][dy][2*j+1], d1, n1);
                    rx[dy][2*j]   = n0/(d0+EPSV)+bia;
                    rx[dy][2*j+1] = n1/(d1+EPSV)+bia;
                    rc[dy][2*j]   = d0*rsa;
                    rc[dy][2*j+1] = d1*rsa;
                }
                float4* dst = (float4*)(out + (size_t)(b*2+a)*P + (size_t)(gyp+dy)*W + gx);
                dst[0] = make_float4(rc[dy][0], rx[dy][0]*rc[dy][0],
                                     rc[dy][1], rx[dy][1]*rc[dy][1]);
                dst[1] = make_float4(rc[dy][2], rx[dy][2]*rc[dy][2],
                                     rc[dy][3], rx[dy][3]*rc[dy][3]);
            }
            if(POOL){
                float pc[2], px[2];
                #pragma unroll
                for(int cell=0;cell<2;cell++){
                    int c0 = 2*cell;
                    float bc = rc[0][c0],  bxv = rx[0][c0];
                    if(rc[0][c0+1]>bc){ bc=rc[0][c0+1]; bxv=rx[0][c0+1]; }
                    if(rc[1][c0]  >bc){ bc=rc[1][c0];   bxv=rx[1][c0];   }
                    if(rc[1][c0+1]>bc){ bc=rc[1][c0+1]; bxv=rx[1][c0+1]; }
                    pc[cell] = bc*0.25f;
                    px[cell] = bxv;
                }
                float4* pdst = (float4*)(outds + (size_t)(b*2+a)*Ph + (size_t)(gyp>>1)*Wh + (gx>>1));
                pdst[0] = make_float4(pc[0], px[0]*pc[0], pc[1], px[1]*pc[1]);
            }
        }
    }
}

// ---------------- tiled 3x3 cat nconv, interleaved I/O, opt. fused 1x1 -----
#define TX3 64
#define TY3 16
#define SW3 (TX3+2)   // 66
#define SH3 (TY3+2)   // 18

template<bool UP_FIRST, int WOFF, int LYR, bool FUSE_OUT>
__global__ void __launch_bounds__(128,6)
k_nconv3t(const float2* __restrict__ na, const float2* __restrict__ ub,
          float2* __restrict__ out,
          float* __restrict__ xof, float* __restrict__ cof,
          int H, int W, int bpr, int bpc){
    __shared__ __align__(16) float2 sm[4][SH3*SW3];
    __shared__ __align__(16) ull wpk2[72];
    __shared__ float wex[8];

    const int t = threadIdx.x;
    const int P = H*W;
    const int Wh = W>>1, Ph = (W>>1)*(H>>1);

    for(int i=t;i<72;i+=128) wpk2[i]=g_wd[WOFF+i];
    if(t<2){ wex[t]=g_ws[2*LYR+t]; wex[2+t]=g_ws[16+2*LYR+t]; }
    if(FUSE_OUT && t==0){
        float lo, hi;
        unpack2(g_wd[466], lo, hi); wex[4]=lo;       // w7_0
        unpack2(g_wd[468], lo, hi); wex[5]=lo;       // w7_1
        wex[6]=1.0f/g_ws[12];                        // 1/sum7
        wex[7]=g_ws[28];                             // bias7
    }

    int bx = blockIdx.x % bpr;
    int tmp = blockIdx.x / bpr;
    int by = tmp % bpc;
    int b  = tmp / bpc;
    int gx0 = bx*TX3 - 1;
    int gy0 = by*TY3 - 1;

    const bool inter = (gx0>=0) && (gy0>=0) && (gx0+SW3<=W) && (gy0+SH3<=H);
    const int fx = t & 31, fy = t >> 5;

    #pragma unroll
    for(int ci=0;ci<4;ci++){
        const bool fromUp = UP_FIRST ? (ci<2) : (ci>=2);
        const int ch = fromUp ? (UP_FIRST ? ci : ci-2) : (UP_FIRST ? ci-2 : ci);
        const float2* src = fromUp ? (ub + (size_t)(b*2+ch)*Ph) : (na + (size_t)(b*2+ch)*P);
        if(inter){
            #pragma unroll
            for(int ly=fy; ly<SH3; ly+=4){
                int gy = gy0+ly;
                float2* srow = &sm[ci][ly*SW3];
                if(fromUp){
                    const float2* grow = src + (size_t)(gy>>1)*Wh;
                    #pragma unroll
                    for(int lx=fx; lx<SW3; lx+=32)
                        srow[lx] = grow[(gx0+lx)>>1];
                } else {
                    const float2* grow = src + (size_t)gy*W + gx0;
                    #pragma unroll
                    for(int lx=fx; lx<SW3; lx+=32)
                        srow[lx] = grow[lx];
                }
            }
        } else {
            #pragma unroll
            for(int ly=fy; ly<SH3; ly+=4){
                int gy = gy0+ly;
                float2* srow = &sm[ci][ly*SW3];
                #pragma unroll
                for(int lx=fx; lx<SW3; lx+=32){
                    int gx = gx0+lx;
                    float2 v = make_float2(0.f, 0.f);
                    if((unsigned)gx<(unsigned)W && (unsigned)gy<(unsigned)H)
                        v = fromUp ? src[(size_t)(gy>>1)*Wh + (gx>>1)]
                                   : src[(size_t)gy*W + gx];
                    srow[lx] = v;
                }
            }
        }
    }
    __syncthreads();

    const int tx = (t & 15)*4;
    const int ty = (t >> 4)*2;

    ull acc[2][2][4];
    #pragma unroll
    for(int a=0;a<2;a++)
      #pragma unroll
      for(int dy=0;dy<2;dy++)
        #pragma unroll
        for(int dx=0;dx<4;dx++) acc[a][dy][dx]=0ull;

    #pragma unroll
    for(int ci=0;ci<4;ci++){
        ull v[2][6];
        {
            const longlong2* p = (const longlong2*)&sm[ci][ty*SW3 + tx];
            #pragma unroll
            for(int j=0;j<3;j++){ longlong2 q=p[j]; v[0][2*j]=(ull)q.x; v[0][2*j+1]=(ull)q.y; }
        }
        #pragma unroll
        for(int ky=0;ky<3;ky++){
            const int cur = ky & 1, nxt = (ky+1) & 1;
            {
                const longlong2* p = (const longlong2*)&sm[ci][(ty+ky+1)*SW3 + tx];
                #pragma unroll
                for(int j=0;j<3;j++){ longlong2 q=p[j]; v[nxt][2*j]=(ull)q.x; v[nxt][2*j+1]=(ull)q.y; }
            }
            #pragma unroll
            for(int kx=0;kx<3;kx++){
                longlong2 wp = *(const longlong2*)&wpk2[(ci*9 + ky*3 + kx)*2];
                ull wa=(ull)wp.x, wb=(ull)wp.y;
                #pragma unroll
                for(int dx=0;dx<4;dx++){
                    acc[0][0][dx]=fma2(wa, v[cur][kx+dx], acc[0][0][dx]);
                    acc[1][0][dx]=fma2(wb, v[cur][kx+dx], acc[1][0][dx]);
                    acc[0][1][dx]=fma2(wa, v[nxt][kx+dx], acc[0][1][dx]);
                    acc[1][1][dx]=fma2(wb, v[nxt][kx+dx], acc[1][1][dx]);
                }
            }
        }
    }

    float rs0 = 1.0f/wex[0];
    float rs1 = 1.0f/wex[1];
    float bi0 = wex[2];
    float bi1 = wex[3];
    int gx = bx*TX3 + tx;
    if(gx < W){
        #pragma unroll
        for(int dy=0;dy<2;dy++){
            int gy = by*TY3 + ty + dy;
            if(gy>=H) continue;
            float xc[2][4], cc[2][4];
            #pragma unroll
            for(int a=0;a<2;a++){
                float d0,n0,d1,n1,d2,n2,d3,n3;
                unpack2(acc[a][dy][0], d0, n0);
                unpack2(acc[a][dy][1], d1, n1);
                unpack2(acc[a][dy][2], d2, n2);
                unpack2(acc[a][dy][3], d3, n3);
                float bia = a ? bi1 : bi0;
                float rsa = a ? rs1 : rs0;
                xc[a][0] = n0/(d0+EPSV)+bia; xc[a][1] = n1/(d1+EPSV)+bia;
                xc[a][2] = n2/(d2+EPSV)+bia; xc[a][3] = n3/(d3+EPSV)+bia;
                cc[a][0] = d0*rsa; cc[a][1] = d1*rsa;
                cc[a][2] = d2*rsa; cc[a][3] = d3*rsa;
            }
            if(!FUSE_OUT){
                #pragma unroll
                for(int a=0;a<2;a++){
                    float4* dst = (float4*)(out + (size_t)(b*2+a)*P + (size_t)gy*W + gx);
                    dst[0] = make_float4(cc[a][0], xc[a][0]*cc[a][0],
                                         cc[a][1], xc[a][1]*cc[a][1]);
                    dst[1] = make_float4(cc[a][2], xc[a][2]*cc[a][2],
                                         cc[a][3], xc[a][3]*cc[a][3]);
                }
            } else {
                float w70 = wex[4], w71 = wex[5], rs7 = wex[6], bi7 = wex[7];
                float4 XO, CO;
                #pragma unroll
                for(int k=0;k<4;k++){
                    float den = w70*cc[0][k] + w71*cc[1][k];
                    float nom = w70*xc[0][k]*cc[0][k] + w71*xc[1][k]*cc[1][k];
                    ((float*)&XO)[k] = nom/(den+EPSV) + bi7;
                    ((float*)&CO)[k] = den*rs7;
                }
                size_t o = (size_t)b*P + (size_t)gy*W + gx;
                *(float4*)&xof[o] = XO;
                *(float4*)&cof[o] = CO;
            }
        }
    }
}

extern "C" void kernel_launch(void* const* d_in, const int* in_sizes, int n_in,
                              void* d_out, int out_size){
    const float* x0 = (const float*)d_in[0];
    const float* c0 = (const float*)d_in[1];
    const float* w1 = (const float*)d_in[2];  const float* b1 = (const float*)d_in[3];
    const float* w2 = (const float*)d_in[4];  const float* b2 = (const float*)d_in[5];
    const float* w3 = (const float*)d_in[6];  const float* b3 = (const float*)d_in[7];
    const float* w4 = (const float*)d_in[8];  const float* b4 = (const float*)d_in[9];
    const float* w5 = (const float*)d_in[10]; const float* b5 = (const float*)d_in[11];
    const float* w6 = (const float*)d_in[12]; const float* b6 = (const float*)d_in[13];
    const float* w7 = (const float*)d_in[14]; const float* b7 = (const float*)d_in[15];

    float2* S = nullptr;  cudaGetSymbolAddress((void**)&S,  g_scratch);

    float2 *A  = S,        *Bv = S + M0,     *T1 = S + 2*M0;
    float2 *HA = S + 3*M0, *HB = HA + M1,    *T2 = HA + 2*M1;
    float2 *Q  = HA + 3*M1,*T3 = Q + M2,     *T34= Q + 2*M2;
    float2 *E  = Q + 3*M2, *T4 = E + M3;

    auto tiles = [&](int H, int W, int &bpr, int &bpc)->int{
        bpr = (W + TX5 - 1)/TX5; bpc = (H + TY5 - 1)/TY5;
        return bpr*bpc*BB;
    };

    k_prep<<<1,128>>>(w1,b1,w2,b2,w3,b3,w4,b4,w5,b5,w6,b6,w7,b7);

    int bpr, bpc, g;

    // encoder full res (3rd layer fuses pool -> level-1 inputs)
    g = tiles(H0,W0,bpr,bpc);
    k_nconv5t<1,0,0,false,true>   <<<g,128>>>(nullptr, x0, c0, A, nullptr, H0, W0, bpr, bpc);
    k_nconv5t<2,50,1,false,false> <<<g,128>>>(A, nullptr, nullptr, Bv, nullptr, H0, W0, bpr, bpc);
    k_nconv5t<2,150,2,true,false> <<<g,128>>>(Bv, nullptr, nullptr, T1, HA, H0, W0, bpr, bpc);

    // level 1 (2nd layer fuses pool -> level-2 inputs)
    g = tiles(H1,W1,bpr,bpc);
    k_nconv5t<2,50,1,false,false> <<<g,128>>>(HA, nullptr, nullptr, HB, nullptr, H1, W1, bpr, bpc);
    k_nconv5t<2,150,2,true,false> <<<g,128>>>(HB, nullptr, nullptr, T2, Q, H1, W1, bpr, bpc);

    // level 2 (fuses pool -> level-3 inputs)
    g = tiles(H2,W2,bpr,bpc);
    k_nconv5t<2,50,1,true,false>  <<<g,128>>>(Q, nullptr, nullptr, T3, E, H2, W2, bpr, bpc);

    // level 3
    g = tiles(H3,W3,bpr,bpc);
    k_nconv5t<2,50,1,false,false> <<<g,128>>>(E, nullptr, nullptr, T4, nullptr, H3, W3, bpr, bpc);

    // decoder (last stage fuses the final 1x1 nconv directly into d_out)
    float* out = (float*)d_out;
    bpr = (W2+TX3-1)/TX3; bpc = (H2+TY3-1)/TY3; g = bpr*bpc*BB;
    k_nconv3t<false,250,3,false><<<g,128>>>(T3, T4,  T34, nullptr, nullptr, H2, W2, bpr, bpc);
    bpr = (W1+TX3-1)/TX3; bpc = (H1+TY3-1)/TY3; g = bpr*bpc*BB;
    k_nconv3t<false,322,4,false><<<g,128>>>(T2, T34, HA,  nullptr, nullptr, H1, W1, bpr, bpc);
    bpr = (W0+TX3-1)/TX3; bpc = (H0+TY3-1)/TY3; g = bpr*bpc*BB;
    k_nconv3t<true,394,5,true>  <<<g,128>>>(T1, HA,  nullptr,
                                            out, out + (size_t)BB*P0, H0, W0, bpr, bpc);
}